// round 1
// baseline (speedup 1.0000x reference)
#include <cuda_runtime.h>

// Problem constants
#define SS   1024
#define TT_  1024
#define BB   32
#define DD   1024
#define AA   1024

// Scratch: __device__ globals (no allocation allowed in kernel_launch)
__device__ float g_ts[(size_t)SS * BB * AA];   // (S,B,A) 128 MiB
__device__ float g_tt[(size_t)TT_ * BB * AA];  // (T,B,A) 128 MiB
__device__ float g_sc[(size_t)BB * TT_ * SS];  // (B,T,S) 128 MiB

// ---------------------------------------------------------------------------
// C[m,n] = sum_k A[m,k] * B[n,k]   (NT form), strided batched.
// Tile 128x128x16, 256 threads, 8x8 per thread.
// ---------------------------------------------------------------------------
__global__ __launch_bounds__(256) void gemm_nt_kernel(
    const float* __restrict__ A, const float* __restrict__ Bm, float* __restrict__ C,
    long lda, long ldb, long ldc,
    long batchA, long batchB, long batchC, int K)
{
    A  += (size_t)blockIdx.z * batchA;
    Bm += (size_t)blockIdx.z * batchB;
    C  += (size_t)blockIdx.z * batchC;

    __shared__ float As[16][128];
    __shared__ float Bs[16][128];

    const int tid = threadIdx.x;
    const int tx  = tid & 15;   // column group (8 cols)
    const int ty  = tid >> 4;   // row group (8 rows)
    const long bm = (long)blockIdx.y * 128;
    const long bn = (long)blockIdx.x * 128;

    const int lrow = tid >> 2;         // 0..63
    const int lcol = (tid & 3) << 2;   // 0,4,8,12

    float acc[8][8] = {};

    for (int k0 = 0; k0 < K; k0 += 16) {
        #pragma unroll
        for (int i = 0; i < 2; i++) {
            const int r = lrow + i * 64;
            float4 va = *(const float4*)(A + (bm + r) * lda + k0 + lcol);
            As[lcol + 0][r] = va.x;
            As[lcol + 1][r] = va.y;
            As[lcol + 2][r] = va.z;
            As[lcol + 3][r] = va.w;
            float4 vb = *(const float4*)(Bm + (bn + r) * ldb + k0 + lcol);
            Bs[lcol + 0][r] = vb.x;
            Bs[lcol + 1][r] = vb.y;
            Bs[lcol + 2][r] = vb.z;
            Bs[lcol + 3][r] = vb.w;
        }
        __syncthreads();
        #pragma unroll
        for (int kk = 0; kk < 16; kk++) {
            float ra[8], rb[8];
            *(float4*)&ra[0] = *(const float4*)&As[kk][ty * 8];
            *(float4*)&ra[4] = *(const float4*)&As[kk][ty * 8 + 4];
            *(float4*)&rb[0] = *(const float4*)&Bs[kk][tx * 8];
            *(float4*)&rb[4] = *(const float4*)&Bs[kk][tx * 8 + 4];
            #pragma unroll
            for (int i = 0; i < 8; i++)
                #pragma unroll
                for (int j = 0; j < 8; j++)
                    acc[i][j] = fmaf(ra[i], rb[j], acc[i][j]);
        }
        __syncthreads();
    }

    #pragma unroll
    for (int i = 0; i < 8; i++) {
        float* cp = C + (bm + ty * 8 + i) * ldc + bn + tx * 8;
        *(float4*)(cp)     = make_float4(acc[i][0], acc[i][1], acc[i][2], acc[i][3]);
        *(float4*)(cp + 4) = make_float4(acc[i][4], acc[i][5], acc[i][6], acc[i][7]);
    }
}

// ---------------------------------------------------------------------------
// C[m,n] = sum_k A[m,k] * B[k,n]   (NN form), strided batched.
// ---------------------------------------------------------------------------
__global__ __launch_bounds__(256) void gemm_nn_kernel(
    const float* __restrict__ A, const float* __restrict__ Bm, float* __restrict__ C,
    long lda, long ldb, long ldc,
    long batchA, long batchB, long batchC, int K)
{
    A  += (size_t)blockIdx.z * batchA;
    Bm += (size_t)blockIdx.z * batchB;
    C  += (size_t)blockIdx.z * batchC;

    __shared__ float As[16][128];
    __shared__ float Bs[16][128];

    const int tid = threadIdx.x;
    const int tx  = tid & 15;
    const int ty  = tid >> 4;
    const long bm = (long)blockIdx.y * 128;
    const long bn = (long)blockIdx.x * 128;

    const int lrow = tid >> 2;         // 0..63 (A tile)
    const int lcol = (tid & 3) << 2;   // 0,4,8,12
    const int brow = tid >> 5;         // 0..7  (B tile: 16x128)
    const int bcol = (tid & 31) << 2;  // 0..124

    float acc[8][8] = {};

    for (int k0 = 0; k0 < K; k0 += 16) {
        #pragma unroll
        for (int i = 0; i < 2; i++) {
            const int r = lrow + i * 64;
            float4 va = *(const float4*)(A + (bm + r) * lda + k0 + lcol);
            As[lcol + 0][r] = va.x;
            As[lcol + 1][r] = va.y;
            As[lcol + 2][r] = va.z;
            As[lcol + 3][r] = va.w;
            const int rr = brow + i * 8;
            float4 vb = *(const float4*)(Bm + (long)(k0 + rr) * ldb + bn + bcol);
            *(float4*)&Bs[rr][bcol] = vb;
        }
        __syncthreads();
        #pragma unroll
        for (int kk = 0; kk < 16; kk++) {
            float ra[8], rb[8];
            *(float4*)&ra[0] = *(const float4*)&As[kk][ty * 8];
            *(float4*)&ra[4] = *(const float4*)&As[kk][ty * 8 + 4];
            *(float4*)&rb[0] = *(const float4*)&Bs[kk][tx * 8];
            *(float4*)&rb[4] = *(const float4*)&Bs[kk][tx * 8 + 4];
            #pragma unroll
            for (int i = 0; i < 8; i++)
                #pragma unroll
                for (int j = 0; j < 8; j++)
                    acc[i][j] = fmaf(ra[i], rb[j], acc[i][j]);
        }
        __syncthreads();
    }

    #pragma unroll
    for (int i = 0; i < 8; i++) {
        float* cp = C + (bm + ty * 8 + i) * ldc + bn + tx * 8;
        *(float4*)(cp)     = make_float4(acc[i][0], acc[i][1], acc[i][2], acc[i][3]);
        *(float4*)(cp + 4) = make_float4(acc[i][4], acc[i][5], acc[i][6], acc[i][7]);
    }
}

// ---------------------------------------------------------------------------
// In-place softmax over the last (contiguous) dim of g_sc: rows of 1024.
// One block of 256 threads per row; each thread owns one float4.
// ---------------------------------------------------------------------------
__global__ __launch_bounds__(256) void softmax_kernel(float* __restrict__ sc)
{
    float4* p = (float4*)(sc + (size_t)blockIdx.x * 1024);
    const int tid = threadIdx.x;
    __shared__ float sh[8];

    float4 v = p[tid];

    // max reduce
    float m = fmaxf(fmaxf(v.x, v.y), fmaxf(v.z, v.w));
    #pragma unroll
    for (int o = 16; o; o >>= 1) m = fmaxf(m, __shfl_xor_sync(0xffffffffu, m, o));
    if ((tid & 31) == 0) sh[tid >> 5] = m;
    __syncthreads();
    m = sh[0];
    #pragma unroll
    for (int i = 1; i < 8; i++) m = fmaxf(m, sh[i]);
    __syncthreads();

    // exp + sum reduce
    v.x = __expf(v.x - m);
    v.y = __expf(v.y - m);
    v.z = __expf(v.z - m);
    v.w = __expf(v.w - m);
    float s = v.x + v.y + v.z + v.w;
    #pragma unroll
    for (int o = 16; o; o >>= 1) s += __shfl_xor_sync(0xffffffffu, s, o);
    if ((tid & 31) == 0) sh[tid >> 5] = s;
    __syncthreads();
    s = sh[0] + sh[1] + sh[2] + sh[3] + sh[4] + sh[5] + sh[6] + sh[7];

    const float inv = 1.0f / s;
    v.x *= inv; v.y *= inv; v.z *= inv; v.w *= inv;
    p[tid] = v;
}

// ---------------------------------------------------------------------------
// kernel_launch: 5 sequential launches on the default stream (graph-capturable,
// allocation-free; scratch lives in __device__ globals).
// ---------------------------------------------------------------------------
extern "C" void kernel_launch(void* const* d_in, const int* in_sizes, int n_in,
                              void* d_out, int out_size)
{
    const float* src = (const float*)d_in[0];  // (S,B,D)
    const float* tgt = (const float*)d_in[1];  // (T,B,D)
    const float* W1  = (const float*)d_in[2];  // (A,D)
    const float* W2  = (const float*)d_in[3];  // (A,D)
    float* out = (float*)d_out;                // (T,B,D)

    float *ts, *tt, *sc;
    cudaGetSymbolAddress((void**)&ts, g_ts);
    cudaGetSymbolAddress((void**)&tt, g_tt);
    cudaGetSymbolAddress((void**)&sc, g_sc);

    dim3 blk(256);

    // Phase 1: ts[(s*B+b), a] = sum_d source[(s*B+b), d] * W1[a, d]
    //   M = S*B = 32768, N = A = 1024, K = D = 1024
    gemm_nt_kernel<<<dim3(8, 256, 1), blk>>>(src, W1, ts,
        1024, 1024, 1024, 0, 0, 0, 1024);

    // Phase 2: tt for target/W2
    gemm_nt_kernel<<<dim3(8, 256, 1), blk>>>(tgt, W2, tt,
        1024, 1024, 1024, 0, 0, 0, 1024);

    // Phase 3: scores[b][t][s] = sum_a tt[t,b,a] * ts[s,b,a]   (batched over b)
    //   A = tt_b  (M=T, row stride B*A), B = ts_b (N=S, row stride B*A)
    gemm_nt_kernel<<<dim3(8, 8, 32), blk>>>(tt, ts, sc,
        (long)BB * AA, (long)BB * AA, SS,
        AA, AA, (long)TT_ * SS, AA);

    // Phase 4: softmax over s (contiguous last dim), in place
    softmax_kernel<<<BB * TT_, blk>>>(sc);

    // Phase 5: out[t,b,d] = sum_s weights[b,t,s] * source[s,b,d]  (batched over b)
    //   A = sc_b (M=T, lda=S), B = src_b (k=s rows, row stride B*D), C = out_b
    gemm_nn_kernel<<<dim3(8, 8, 32), blk>>>(sc, src, out,
        SS, (long)BB * DD, (long)BB * DD,
        (long)TT_ * SS, DD, DD, SS);
}

// round 3
// speedup vs baseline: 2.8373x; 2.8373x over previous
#include <cuda_runtime.h>
#include <cuda_bf16.h>
#include <cstdint>

typedef __nv_bfloat16 bf16;

#define S_ 1024
#define T_ 1024
#define B_ 32
#define D_ 1024
#define A_ 1024

// ---------------------------------------------------------------------------
// Scratch (device globals; allocation is forbidden)
// ---------------------------------------------------------------------------
__device__ __align__(16) bf16 g_srcHi[(size_t)S_ * B_ * D_];   // (S,B,D)
__device__ __align__(16) bf16 g_srcLo[(size_t)S_ * B_ * D_];
__device__ __align__(16) bf16 g_tgtHi[(size_t)T_ * B_ * D_];   // (T,B,D)
__device__ __align__(16) bf16 g_tgtLo[(size_t)T_ * B_ * D_];
__device__ __align__(16) bf16 g_mtHi[(size_t)A_ * D_];         // Mt[e,d] = sum_a W2[a,e]W1[a,d]
__device__ __align__(16) bf16 g_mtLo[(size_t)A_ * D_];
__device__ __align__(16) bf16 g_uHi[(size_t)S_ * B_ * A_];     // (S,B,A) u = src @ Mt^T
__device__ __align__(16) bf16 g_uLo[(size_t)S_ * B_ * A_];
__device__ __align__(16) float g_sc[(size_t)B_ * T_ * S_];     // (B,T,S) scores
__device__ __align__(16) bf16 g_wHi[(size_t)B_ * T_ * S_];     // softmax weights split
__device__ __align__(16) bf16 g_wLo[(size_t)B_ * T_ * S_];

// ---------------------------------------------------------------------------
// Portable tensor-core primitives (sm_80-level PTX: compiles for compute_103)
// ---------------------------------------------------------------------------
__device__ __forceinline__ uint32_t smem_u32(const void* p) {
    uint32_t a;
    asm("{ .reg .u64 t; cvta.to.shared.u64 t, %1; cvt.u32.u64 %0, t; }" : "=r"(a) : "l"(p));
    return a;
}

__device__ __forceinline__ void cpa16(uint32_t s, const void* g) {
    asm volatile("cp.async.cg.shared.global [%0], [%1], 16;" :: "r"(s), "l"(g));
}
#define CP_COMMIT() asm volatile("cp.async.commit_group;" ::: "memory")
#define CP_WAIT2()  asm volatile("cp.async.wait_group 2;" ::: "memory")

__device__ __forceinline__ void ldsm4(uint32_t* r, uint32_t a) {
    asm volatile("ldmatrix.sync.aligned.m8n8.x4.shared.b16 {%0,%1,%2,%3}, [%4];"
                 : "=r"(r[0]), "=r"(r[1]), "=r"(r[2]), "=r"(r[3]) : "r"(a));
}
__device__ __forceinline__ void ldsm4t(uint32_t* r, uint32_t a) {
    asm volatile("ldmatrix.sync.aligned.m8n8.x4.trans.shared.b16 {%0,%1,%2,%3}, [%4];"
                 : "=r"(r[0]), "=r"(r[1]), "=r"(r[2]), "=r"(r[3]) : "r"(a));
}
__device__ __forceinline__ void mma_bf16(float* c, const uint32_t* a, const uint32_t* b) {
    asm volatile("mma.sync.aligned.m16n8k16.row.col.f32.bf16.bf16.f32 "
                 "{%0,%1,%2,%3}, {%4,%5,%6,%7}, {%8,%9}, {%0,%1,%2,%3};"
                 : "+f"(c[0]), "+f"(c[1]), "+f"(c[2]), "+f"(c[3])
                 : "r"(a[0]), "r"(a[1]), "r"(a[2]), "r"(a[3]), "r"(b[0]), "r"(b[1]));
}

// ---------------------------------------------------------------------------
// Tiled bf16x3-split GEMM:  C[m,n](z) = sum_k A[m,k]*B[n,k]  (NT)
//   or, if BTRANS:          C[m,n](z) = sum_k A[m,k]*B[k,n]  (B loaded via ldmatrix.trans)
// CTA tile 128x128x32, 8 warps (2x4 -> 64x32 warp tiles), 3-stage cp.async ring.
// Per (m,n,k) fragment: acc += Ahi*Bhi + Ahi*Blo + Alo*Bhi.
// ---------------------------------------------------------------------------
#define STAGE_B  40960
#define SM_TOTAL (3 * STAGE_B)
// stage offsets: Ahi 0, Alo 10240, Bhi 20480, Blo 30720
// A/B(non-trans) tile: 128 rows x 32 bf16, row stride 80B (pad -> conflict-free ldsm)
// B(trans) tile:        32 rows x 128 bf16, row stride 272B

__device__ __forceinline__ void load_tile_nt(uint32_t sbase, const bf16* g, long ld, int tid) {
    #pragma unroll
    for (int i = 0; i < 2; i++) {
        int c = tid + i * 256;            // 512 x 16B chunks
        int row = c >> 2, off = (c & 3) * 8;
        cpa16(sbase + row * 80 + off * 2, g + (long)row * ld + off);
    }
}
__device__ __forceinline__ void load_tile_tr(uint32_t sbase, const bf16* g, long ld, int tid) {
    #pragma unroll
    for (int i = 0; i < 2; i++) {
        int c = tid + i * 256;
        int row = c >> 4, off = (c & 15) * 8;
        cpa16(sbase + row * 272 + off * 2, g + (long)row * ld + off);
    }
}

template <bool BTRANS, bool SPLITOUT>
__global__ __launch_bounds__(256, 1) void mma_gemm(
    const bf16* __restrict__ Ah, const bf16* __restrict__ Al,
    const bf16* __restrict__ Bh, const bf16* __restrict__ Bl,
    float* __restrict__ C, bf16* __restrict__ Oh, bf16* __restrict__ Ol,
    long lda, long ldb, long ldc, long aB, long bB, long cB)
{
    extern __shared__ char smem[];
    const uint32_t sb = smem_u32(smem);
    const int tid = threadIdx.x;
    const int lane = tid & 31, wid = tid >> 5;
    const int wy = wid >> 2, wx = wid & 3;        // 2 x 4 warps
    const long m0 = (long)blockIdx.y * 128;
    const long n0 = (long)blockIdx.x * 128;
    const long z  = blockIdx.z;

    const bf16* pAh = Ah + z * aB + m0 * lda;
    const bf16* pAl = Al + z * aB + m0 * lda;
    const bf16* pBh = BTRANS ? (Bh + z * bB + n0) : (Bh + z * bB + n0 * ldb);
    const bf16* pBl = BTRANS ? (Bl + z * bB + n0) : (Bl + z * bB + n0 * ldb);

    float acc[4][4][4] = {};

    auto LOAD = [&](int chunk) {
        const uint32_t st = sb + (chunk % 3) * STAGE_B;
        const long k0 = (long)chunk * 32;
        load_tile_nt(st,         pAh + k0, lda, tid);
        load_tile_nt(st + 10240, pAl + k0, lda, tid);
        if (BTRANS) {
            load_tile_tr(st + 20480, pBh + k0 * ldb, ldb, tid);
            load_tile_tr(st + 30720, pBl + k0 * ldb, ldb, tid);
        } else {
            load_tile_nt(st + 20480, pBh + k0, ldb, tid);
            load_tile_nt(st + 30720, pBl + k0, ldb, tid);
        }
    };

    LOAD(0); CP_COMMIT();
    LOAD(1); CP_COMMIT();

    const int NC = 32;   // K=1024 / 32
    for (int c = 0; c < NC; c++) {
        if (c + 2 < NC) LOAD(c + 2);
        CP_COMMIT();                     // empty group at tail keeps count uniform
        CP_WAIT2();                      // chunk c resident
        __syncthreads();
        const uint32_t st = sb + (c % 3) * STAGE_B;

        #pragma unroll
        for (int k16 = 0; k16 < 2; k16++) {
            uint32_t ah[4][4], al[4][4], bh[8], bl[8];
            // A fragments (hi+lo): rows [wy*64 .. +63], k half k16
            #pragma unroll
            for (int mt = 0; mt < 4; mt++) {
                uint32_t ad = st + (uint32_t)(wy * 64 + mt * 16 + (lane & 15)) * 80
                            + k16 * 32 + ((lane >> 4) << 4);
                ldsm4(ah[mt], ad);
                ldsm4(al[mt], ad + 10240);
            }
            // B fragments
            if (!BTRANS) {
                #pragma unroll
                for (int p = 0; p < 2; p++) {
                    uint32_t nrow = (uint32_t)(wx * 32 + p * 16 + (lane & 7) + ((lane >> 4) << 3));
                    uint32_t bd = st + 20480 + nrow * 80 + k16 * 32 + (((lane >> 3) & 1) << 4);
                    ldsm4(&bh[p * 4], bd);
                    ldsm4(&bl[p * 4], bd + 10240);
                }
            } else {
                #pragma unroll
                for (int p = 0; p < 2; p++) {
                    uint32_t krow = (uint32_t)(k16 * 16 + (lane & 7) + ((lane >> 3) & 1) * 8);
                    uint32_t ncol = (uint32_t)(wx * 32 + p * 16 + ((lane >> 4) << 3));
                    uint32_t bd = st + 20480 + krow * 272 + ncol * 2;
                    ldsm4t(&bh[p * 4], bd);
                    ldsm4t(&bl[p * 4], bd + 10240);
                }
            }
            // 48 HMMA: hi*hi + hi*lo + lo*hi
            #pragma unroll
            for (int mt = 0; mt < 4; mt++)
                #pragma unroll
                for (int nt = 0; nt < 4; nt++) {
                    mma_bf16(acc[mt][nt], ah[mt], &bh[nt * 2]);
                    mma_bf16(acc[mt][nt], ah[mt], &bl[nt * 2]);
                    mma_bf16(acc[mt][nt], al[mt], &bh[nt * 2]);
                }
        }
        __syncthreads();
    }

    // Epilogue (registers -> gmem)
    #pragma unroll
    for (int mt = 0; mt < 4; mt++) {
        #pragma unroll
        for (int half = 0; half < 2; half++) {
            const long row = m0 + wy * 64 + mt * 16 + (lane >> 2) + half * 8;
            #pragma unroll
            for (int nt = 0; nt < 4; nt++) {
                const long col = n0 + wx * 32 + nt * 8 + (lane & 3) * 2;
                const float v0 = acc[mt][nt][half * 2 + 0];
                const float v1 = acc[mt][nt][half * 2 + 1];
                if (SPLITOUT) {
                    bf16 h0 = __float2bfloat16_rn(v0), h1 = __float2bfloat16_rn(v1);
                    bf16 l0 = __float2bfloat16_rn(v0 - __bfloat162float(h0));
                    bf16 l1 = __float2bfloat16_rn(v1 - __bfloat162float(h1));
                    __nv_bfloat162 hv(h0, h1), lv(l0, l1);
                    *(uint32_t*)(Oh + z * cB + row * ldc + col) = *(uint32_t*)&hv;
                    *(uint32_t*)(Ol + z * cB + row * ldc + col) = *(uint32_t*)&lv;
                } else {
                    *(float2*)(C + z * cB + row * ldc + col) = make_float2(v0, v1);
                }
            }
        }
    }
}

// ---------------------------------------------------------------------------
// Elementwise fp32 -> bf16 hi/lo split
// ---------------------------------------------------------------------------
__global__ __launch_bounds__(256) void split_kernel(
    const float* __restrict__ x, bf16* __restrict__ hi, bf16* __restrict__ lo)
{
    const size_t i4 = (size_t)blockIdx.x * 256 + threadIdx.x;
    float4 v = ((const float4*)x)[i4];
    float f[4] = {v.x, v.y, v.z, v.w};
    uint32_t hw[2], lw[2];
    #pragma unroll
    for (int p = 0; p < 2; p++) {
        bf16 h0 = __float2bfloat16_rn(f[2 * p]), h1 = __float2bfloat16_rn(f[2 * p + 1]);
        bf16 l0 = __float2bfloat16_rn(f[2 * p] - __bfloat162float(h0));
        bf16 l1 = __float2bfloat16_rn(f[2 * p + 1] - __bfloat162float(h1));
        __nv_bfloat162 hv(h0, h1), lv(l0, l1);
        hw[p] = *(uint32_t*)&hv;
        lw[p] = *(uint32_t*)&lv;
    }
    ((uint2*)hi)[i4] = make_uint2(hw[0], hw[1]);
    ((uint2*)lo)[i4] = make_uint2(lw[0], lw[1]);
}

// ---------------------------------------------------------------------------
// TN SIMT fp32 GEMM: Mt[e,d] = sum_a W2[a,e]*W1[a,d], split-stored (2 GFLOP)
// ---------------------------------------------------------------------------
__global__ __launch_bounds__(256) void tn_split_kernel(
    const float* __restrict__ W2, const float* __restrict__ W1)
{
    __shared__ float As[16][128];
    __shared__ float Bs[16][128];

    const int tid = threadIdx.x;
    const int tx = tid & 15, ty = tid >> 4;
    const int m0 = blockIdx.y * 128, n0 = blockIdx.x * 128;
    const int r8 = tid >> 5, c4 = (tid & 31) * 4;

    float acc[8][8] = {};

    for (int k0 = 0; k0 < 1024; k0 += 16) {
        #pragma unroll
        for (int i = 0; i < 2; i++) {
            const int kr = k0 + r8 + i * 8;
            *(float4*)&As[r8 + i * 8][c4] = *(const float4*)(W2 + (size_t)kr * 1024 + m0 + c4);
            *(float4*)&Bs[r8 + i * 8][c4] = *(const float4*)(W1 + (size_t)kr * 1024 + n0 + c4);
        }
        __syncthreads();
        #pragma unroll
        for (int kk = 0; kk < 16; kk++) {
            float ra[8], rb[8];
            *(float4*)&ra[0] = *(const float4*)&As[kk][ty * 8];
            *(float4*)&ra[4] = *(const float4*)&As[kk][ty * 8 + 4];
            *(float4*)&rb[0] = *(const float4*)&Bs[kk][tx * 8];
            *(float4*)&rb[4] = *(const float4*)&Bs[kk][tx * 8 + 4];
            #pragma unroll
            for (int i = 0; i < 8; i++)
                #pragma unroll
                for (int j = 0; j < 8; j++)
                    acc[i][j] = fmaf(ra[i], rb[j], acc[i][j]);
        }
        __syncthreads();
    }

    #pragma unroll
    for (int i = 0; i < 8; i++) {
        const size_t base = (size_t)(m0 + ty * 8 + i) * 1024 + n0 + tx * 8;
        #pragma unroll
        for (int j = 0; j < 8; j++) {
            float f = acc[i][j];
            bf16 h = __float2bfloat16_rn(f);
            g_mtHi[base + j] = h;
            g_mtLo[base + j] = __float2bfloat16_rn(f - __bfloat162float(h));
        }
    }
}

// ---------------------------------------------------------------------------
// Softmax over contiguous rows of 1024; writes bf16 hi/lo split weights.
// ---------------------------------------------------------------------------
__global__ __launch_bounds__(256) void softmax_split_kernel(const float* __restrict__ sc)
{
    const size_t row = blockIdx.x;
    const float4* p = (const float4*)(sc + row * 1024);
    const int tid = threadIdx.x;
    __shared__ float sh[8];

    float4 v = p[tid];

    float m = fmaxf(fmaxf(v.x, v.y), fmaxf(v.z, v.w));
    #pragma unroll
    for (int o = 16; o; o >>= 1) m = fmaxf(m, __shfl_xor_sync(0xffffffffu, m, o));
    if ((tid & 31) == 0) sh[tid >> 5] = m;
    __syncthreads();
    m = sh[0];
    #pragma unroll
    for (int i = 1; i < 8; i++) m = fmaxf(m, sh[i]);
    __syncthreads();

    v.x = __expf(v.x - m); v.y = __expf(v.y - m);
    v.z = __expf(v.z - m); v.w = __expf(v.w - m);
    float s = v.x + v.y + v.z + v.w;
    #pragma unroll
    for (int o = 16; o; o >>= 1) s += __shfl_xor_sync(0xffffffffu, s, o);
    if ((tid & 31) == 0) sh[tid >> 5] = s;
    __syncthreads();
    s = sh[0] + sh[1] + sh[2] + sh[3] + sh[4] + sh[5] + sh[6] + sh[7];
    const float inv = 1.0f / s;

    float f[4] = {v.x * inv, v.y * inv, v.z * inv, v.w * inv};
    uint32_t hw[2], lw[2];
    #pragma unroll
    for (int q = 0; q < 2; q++) {
        bf16 h0 = __float2bfloat16_rn(f[2 * q]), h1 = __float2bfloat16_rn(f[2 * q + 1]);
        bf16 l0 = __float2bfloat16_rn(f[2 * q] - __bfloat162float(h0));
        bf16 l1 = __float2bfloat16_rn(f[2 * q + 1] - __bfloat162float(h1));
        __nv_bfloat162 hv(h0, h1), lv(l0, l1);
        hw[q] = *(uint32_t*)&hv;
        lw[q] = *(uint32_t*)&lv;
    }
    ((uint2*)(g_wHi + row * 1024))[tid] = make_uint2(hw[0], hw[1]);
    ((uint2*)(g_wLo + row * 1024))[tid] = make_uint2(lw[0], lw[1]);
}

// ---------------------------------------------------------------------------
// Host
// ---------------------------------------------------------------------------
extern "C" void kernel_launch(void* const* d_in, const int* in_sizes, int n_in,
                              void* d_out, int out_size)
{
    const float* src = (const float*)d_in[0];  // (S,B,D)
    const float* tgt = (const float*)d_in[1];  // (T,B,D)
    const float* W1  = (const float*)d_in[2];  // (A,D)
    const float* W2  = (const float*)d_in[3];  // (A,D)
    float* out = (float*)d_out;                // (T,B,D)

    void *srcHi, *srcLo, *tgtHi, *tgtLo, *mtHi, *mtLo, *uHi, *uLo, *sc, *wHi, *wLo;
    cudaGetSymbolAddress(&srcHi, g_srcHi); cudaGetSymbolAddress(&srcLo, g_srcLo);
    cudaGetSymbolAddress(&tgtHi, g_tgtHi); cudaGetSymbolAddress(&tgtLo, g_tgtLo);
    cudaGetSymbolAddress(&mtHi, g_mtHi);   cudaGetSymbolAddress(&mtLo, g_mtLo);
    cudaGetSymbolAddress(&uHi, g_uHi);     cudaGetSymbolAddress(&uLo, g_uLo);
    cudaGetSymbolAddress(&sc, g_sc);
    cudaGetSymbolAddress(&wHi, g_wHi);     cudaGetSymbolAddress(&wLo, g_wLo);

    cudaFuncSetAttribute(mma_gemm<false, true>,  cudaFuncAttributeMaxDynamicSharedMemorySize, SM_TOTAL);
    cudaFuncSetAttribute(mma_gemm<false, false>, cudaFuncAttributeMaxDynamicSharedMemorySize, SM_TOTAL);
    cudaFuncSetAttribute(mma_gemm<true,  false>, cudaFuncAttributeMaxDynamicSharedMemorySize, SM_TOTAL);

    // 1-2. split source & target into bf16 hi/lo
    split_kernel<<<(S_ * B_ * D_ / 4) / 256, 256>>>(src, (bf16*)srcHi, (bf16*)srcLo);
    split_kernel<<<(T_ * B_ * D_ / 4) / 256, 256>>>(tgt, (bf16*)tgtHi, (bf16*)tgtLo);
    // 3. Mt = W2^T W1 (fp32 SIMT), split-stored
    tn_split_kernel<<<dim3(8, 8), 256>>>(W2, W1);

    // 4. u[(s,b), e] = sum_d src[(s,b), d] * Mt[e, d]   (NT, M=32768, split output)
    mma_gemm<false, true><<<dim3(8, 256, 1), 256, SM_TOTAL>>>(
        (const bf16*)srcHi, (const bf16*)srcLo, (const bf16*)mtHi, (const bf16*)mtLo,
        nullptr, (bf16*)uHi, (bf16*)uLo,
        1024, 1024, 1024, 0, 0, 0);

    // 5. scores[b,t,s] = sum_e tgt[t,b,e] * u[s,b,e]   (NT, batched over b)
    mma_gemm<false, false><<<dim3(8, 8, 32), 256, SM_TOTAL>>>(
        (const bf16*)tgtHi, (const bf16*)tgtLo, (const bf16*)uHi, (const bf16*)uLo,
        (float*)sc, nullptr, nullptr,
        32768, 32768, 1024, 1024, 1024, (long)1024 * 1024);

    // 6. softmax over s (+ split weights)
    softmax_split_kernel<<<B_ * T_, 256>>>((const float*)sc);

    // 7. out[t,b,d] = sum_s w[b,t,s] * src[s,b,d]   (A NT, B via ldmatrix.trans)
    mma_gemm<true, false><<<dim3(8, 8, 32), 256, SM_TOTAL>>>(
        (const bf16*)wHi, (const bf16*)wLo, (const bf16*)srcHi, (const bf16*)srcLo,
        out, nullptr, nullptr,
        1024, 32768, 32768, (long)1024 * 1024, 1024, 1024);
}

// round 4
// speedup vs baseline: 2.9729x; 1.0478x over previous
#include <cuda_runtime.h>
#include <cuda_bf16.h>
#include <cstdint>

typedef __nv_bfloat16 bf16;

#define S_ 1024
#define T_ 1024
#define B_ 32
#define D_ 1024
#define A_ 1024

// ---------------------------------------------------------------------------
// Scratch (device globals; allocation is forbidden)
// ---------------------------------------------------------------------------
__device__ __align__(16) bf16 g_srcHi[(size_t)S_ * B_ * D_];   // (S,B,D)
__device__ __align__(16) bf16 g_srcLo[(size_t)S_ * B_ * D_];
__device__ __align__(16) bf16 g_tgtHi[(size_t)T_ * B_ * D_];   // (T,B,D)
__device__ __align__(16) bf16 g_tgtLo[(size_t)T_ * B_ * D_];
__device__ __align__(16) bf16 g_mtHi[(size_t)A_ * D_];         // Mt[e,d] = sum_a W2[a,e]W1[a,d]
__device__ __align__(16) bf16 g_mtLo[(size_t)A_ * D_];
__device__ __align__(16) bf16 g_uHi[(size_t)S_ * B_ * A_];     // (S,B,A) u = src @ Mt^T
__device__ __align__(16) bf16 g_uLo[(size_t)S_ * B_ * A_];
__device__ __align__(16) float g_sc[(size_t)B_ * T_ * S_];     // (B,T,S) scores
__device__ __align__(16) bf16 g_wHi[(size_t)B_ * T_ * S_];     // softmax weights split
__device__ __align__(16) bf16 g_wLo[(size_t)B_ * T_ * S_];

// ---------------------------------------------------------------------------
// Portable tensor-core primitives (sm_80-level PTX: safe for compute_103 pass)
// ---------------------------------------------------------------------------
__device__ __forceinline__ uint32_t smem_u32(const void* p) {
    uint32_t a;
    asm("{ .reg .u64 t; cvta.to.shared.u64 t, %1; cvt.u32.u64 %0, t; }" : "=r"(a) : "l"(p));
    return a;
}

__device__ __forceinline__ void cpa16(uint32_t s, const void* g) {
    asm volatile("cp.async.cg.shared.global [%0], [%1], 16;" :: "r"(s), "l"(g));
}
#define CP_COMMIT() asm volatile("cp.async.commit_group;" ::: "memory")
#define CP_WAIT1()  asm volatile("cp.async.wait_group 1;" ::: "memory")

__device__ __forceinline__ void ldsm4(uint32_t* r, uint32_t a) {
    asm volatile("ldmatrix.sync.aligned.m8n8.x4.shared.b16 {%0,%1,%2,%3}, [%4];"
                 : "=r"(r[0]), "=r"(r[1]), "=r"(r[2]), "=r"(r[3]) : "r"(a));
}
__device__ __forceinline__ void ldsm4t(uint32_t* r, uint32_t a) {
    asm volatile("ldmatrix.sync.aligned.m8n8.x4.trans.shared.b16 {%0,%1,%2,%3}, [%4];"
                 : "=r"(r[0]), "=r"(r[1]), "=r"(r[2]), "=r"(r[3]) : "r"(a));
}
__device__ __forceinline__ void mma_bf16(float* c, const uint32_t* a, const uint32_t* b) {
    asm volatile("mma.sync.aligned.m16n8k16.row.col.f32.bf16.bf16.f32 "
                 "{%0,%1,%2,%3}, {%4,%5,%6,%7}, {%8,%9}, {%0,%1,%2,%3};"
                 : "+f"(c[0]), "+f"(c[1]), "+f"(c[2]), "+f"(c[3])
                 : "r"(a[0]), "r"(a[1]), "r"(a[2]), "r"(a[3]), "r"(b[0]), "r"(b[1]));
}

// ---------------------------------------------------------------------------
// Tiled bf16x3-split GEMM:  C[m,n](z) = sum_k A[m,k]*B[n,k]  (NT)
//   or, if BTRANS:          C[m,n](z) = sum_k A[m,k]*B[k,n]  (B via ldmatrix.trans)
// CTA tile 128x128x32, 16 warps (4x4 -> 32x32 warp tiles), 3-stage cp.async ring,
// one __syncthreads per K-chunk. acc += Ahi*Bhi + Ahi*Blo + Alo*Bhi.
// ---------------------------------------------------------------------------
#define STAGE_B  40960
#define SM_TOTAL (3 * STAGE_B)
// stage layout: Ahi @0 (128x80B), Alo @10240, Bhi @20480, Blo @30720
// B(trans) tile: 32 rows x 272B

__device__ __forceinline__ void load_tile_nt(uint32_t sbase, const bf16* g, long ld, int tid) {
    const int row = tid >> 2, off = (tid & 3) * 8;     // 512 chunks of 16B
    cpa16(sbase + row * 80 + off * 2, g + (long)row * ld + off);
}
__device__ __forceinline__ void load_tile_tr(uint32_t sbase, const bf16* g, long ld, int tid) {
    const int row = tid >> 4, off = (tid & 15) * 8;    // 32 rows x 16 chunks
    cpa16(sbase + row * 272 + off * 2, g + (long)row * ld + off);
}

template <bool BTRANS, bool SPLITOUT>
__global__ __launch_bounds__(512, 1) void mma_gemm(
    const bf16* __restrict__ Ah, const bf16* __restrict__ Al,
    const bf16* __restrict__ Bh, const bf16* __restrict__ Bl,
    float* __restrict__ C, bf16* __restrict__ Oh, bf16* __restrict__ Ol,
    long lda, long ldb, long ldc, long aB, long bB, long cB)
{
    extern __shared__ char smem[];
    const uint32_t sb = smem_u32(smem);
    const int tid = threadIdx.x;
    const int lane = tid & 31, wid = tid >> 5;
    const int wy = wid >> 2, wx = wid & 3;        // 4 x 4 warps, 32x32 tiles
    const long m0 = (long)blockIdx.y * 128;
    const long n0 = (long)blockIdx.x * 128;
    const long z  = blockIdx.z;

    const bf16* pAh = Ah + z * aB + m0 * lda;
    const bf16* pAl = Al + z * aB + m0 * lda;
    const bf16* pBh = BTRANS ? (Bh + z * bB + n0) : (Bh + z * bB + n0 * ldb);
    const bf16* pBl = BTRANS ? (Bl + z * bB + n0) : (Bl + z * bB + n0 * ldb);

    float acc[2][4][4] = {};

    auto LOAD = [&](int chunk) {
        const uint32_t st = sb + (chunk % 3) * STAGE_B;
        const long k0 = (long)chunk * 32;
        load_tile_nt(st,         pAh + k0, lda, tid);
        load_tile_nt(st + 10240, pAl + k0, lda, tid);
        if (BTRANS) {
            load_tile_tr(st + 20480, pBh + k0 * ldb, ldb, tid);
            load_tile_tr(st + 30720, pBl + k0 * ldb, ldb, tid);
        } else {
            load_tile_nt(st + 20480, pBh + k0, ldb, tid);
            load_tile_nt(st + 30720, pBl + k0, ldb, tid);
        }
    };

    LOAD(0); CP_COMMIT();
    LOAD(1); CP_COMMIT();

    const int NC = 32;   // K = 1024 / 32
    for (int c = 0; c < NC; c++) {
        CP_WAIT1();                       // chunk c resident (c+1 may fly)
        __syncthreads();                  // all warps done with stage (c-1)%3
        if (c + 2 < NC) LOAD(c + 2);      // overwrites stage (c-1)%3
        CP_COMMIT();
        const uint32_t st = sb + (c % 3) * STAGE_B;

        #pragma unroll
        for (int k16 = 0; k16 < 2; k16++) {
            uint32_t ah[2][4], al[2][4], bh[8], bl[8];
            #pragma unroll
            for (int mt = 0; mt < 2; mt++) {
                const uint32_t ad = st + (uint32_t)(wy * 32 + mt * 16 + (lane & 15)) * 80
                                  + k16 * 32 + ((lane >> 4) << 4);
                ldsm4(ah[mt], ad);
                ldsm4(al[mt], ad + 10240);
            }
            if (!BTRANS) {
                #pragma unroll
                for (int p = 0; p < 2; p++) {
                    const uint32_t nrow = (uint32_t)(wx * 32 + p * 16 + (lane & 7) + ((lane >> 4) << 3));
                    const uint32_t bd = st + 20480 + nrow * 80 + k16 * 32 + (((lane >> 3) & 1) << 4);
                    ldsm4(&bh[p * 4], bd);
                    ldsm4(&bl[p * 4], bd + 10240);
                }
            } else {
                #pragma unroll
                for (int p = 0; p < 2; p++) {
                    const uint32_t krow = (uint32_t)(k16 * 16 + (lane & 7) + ((lane >> 3) & 1) * 8);
                    const uint32_t ncol = (uint32_t)(wx * 32 + p * 16 + ((lane >> 4) << 3));
                    const uint32_t bd = st + 20480 + krow * 272 + ncol * 2;
                    ldsm4t(&bh[p * 4], bd);
                    ldsm4t(&bl[p * 4], bd + 10240);
                }
            }
            #pragma unroll
            for (int mt = 0; mt < 2; mt++)
                #pragma unroll
                for (int nt = 0; nt < 4; nt++) {
                    mma_bf16(acc[mt][nt], ah[mt], &bh[nt * 2]);
                    mma_bf16(acc[mt][nt], ah[mt], &bl[nt * 2]);
                    mma_bf16(acc[mt][nt], al[mt], &bh[nt * 2]);
                }
        }
    }

    // Epilogue (registers -> gmem)
    #pragma unroll
    for (int mt = 0; mt < 2; mt++) {
        #pragma unroll
        for (int half = 0; half < 2; half++) {
            const long row = m0 + wy * 32 + mt * 16 + (lane >> 2) + half * 8;
            #pragma unroll
            for (int nt = 0; nt < 4; nt++) {
                const long col = n0 + wx * 32 + nt * 8 + (lane & 3) * 2;
                const float v0 = acc[mt][nt][half * 2 + 0];
                const float v1 = acc[mt][nt][half * 2 + 1];
                if (SPLITOUT) {
                    bf16 h0 = __float2bfloat16_rn(v0), h1 = __float2bfloat16_rn(v1);
                    bf16 l0 = __float2bfloat16_rn(v0 - __bfloat162float(h0));
                    bf16 l1 = __float2bfloat16_rn(v1 - __bfloat162float(h1));
                    __nv_bfloat162 hv(h0, h1), lv(l0, l1);
                    *(uint32_t*)(Oh + z * cB + row * ldc + col) = *(uint32_t*)&hv;
                    *(uint32_t*)(Ol + z * cB + row * ldc + col) = *(uint32_t*)&lv;
                } else {
                    *(float2*)(C + z * cB + row * ldc + col) = make_float2(v0, v1);
                }
            }
        }
    }
}

// ---------------------------------------------------------------------------
// Elementwise fp32 -> bf16 hi/lo split
// ---------------------------------------------------------------------------
__global__ __launch_bounds__(256) void split_kernel(
    const float* __restrict__ x, bf16* __restrict__ hi, bf16* __restrict__ lo)
{
    const size_t i4 = (size_t)blockIdx.x * 256 + threadIdx.x;
    float4 v = ((const float4*)x)[i4];
    float f[4] = {v.x, v.y, v.z, v.w};
    uint32_t hw[2], lw[2];
    #pragma unroll
    for (int p = 0; p < 2; p++) {
        bf16 h0 = __float2bfloat16_rn(f[2 * p]), h1 = __float2bfloat16_rn(f[2 * p + 1]);
        bf16 l0 = __float2bfloat16_rn(f[2 * p] - __bfloat162float(h0));
        bf16 l1 = __float2bfloat16_rn(f[2 * p + 1] - __bfloat162float(h1));
        __nv_bfloat162 hv(h0, h1), lv(l0, l1);
        hw[p] = *(uint32_t*)&hv;
        lw[p] = *(uint32_t*)&lv;
    }
    ((uint2*)hi)[i4] = make_uint2(hw[0], hw[1]);
    ((uint2*)lo)[i4] = make_uint2(lw[0], lw[1]);
}

// ---------------------------------------------------------------------------
// TN SIMT fp32 GEMM: Mt[e,d] = sum_a W2[a,e]*W1[a,d], split-stored (2 GFLOP)
// ---------------------------------------------------------------------------
__global__ __launch_bounds__(256) void tn_split_kernel(
    const float* __restrict__ W2, const float* __restrict__ W1)
{
    __shared__ float As[16][128];
    __shared__ float Bs[16][128];

    const int tid = threadIdx.x;
    const int tx = tid & 15, ty = tid >> 4;
    const int m0 = blockIdx.y * 128, n0 = blockIdx.x * 128;
    const int r8 = tid >> 5, c4 = (tid & 31) * 4;

    float acc[8][8] = {};

    for (int k0 = 0; k0 < 1024; k0 += 16) {
        #pragma unroll
        for (int i = 0; i < 2; i++) {
            const int kr = k0 + r8 + i * 8;
            *(float4*)&As[r8 + i * 8][c4] = *(const float4*)(W2 + (size_t)kr * 1024 + m0 + c4);
            *(float4*)&Bs[r8 + i * 8][c4] = *(const float4*)(W1 + (size_t)kr * 1024 + n0 + c4);
        }
        __syncthreads();
        #pragma unroll
        for (int kk = 0; kk < 16; kk++) {
            float ra[8], rb[8];
            *(float4*)&ra[0] = *(const float4*)&As[kk][ty * 8];
            *(float4*)&ra[4] = *(const float4*)&As[kk][ty * 8 + 4];
            *(float4*)&rb[0] = *(const float4*)&Bs[kk][tx * 8];
            *(float4*)&rb[4] = *(const float4*)&Bs[kk][tx * 8 + 4];
            #pragma unroll
            for (int i = 0; i < 8; i++)
                #pragma unroll
                for (int j = 0; j < 8; j++)
                    acc[i][j] = fmaf(ra[i], rb[j], acc[i][j]);
        }
        __syncthreads();
    }

    #pragma unroll
    for (int i = 0; i < 8; i++) {
        const size_t base = (size_t)(m0 + ty * 8 + i) * 1024 + n0 + tx * 8;
        #pragma unroll
        for (int j = 0; j < 8; j++) {
            float f = acc[i][j];
            bf16 h = __float2bfloat16_rn(f);
            g_mtHi[base + j] = h;
            g_mtLo[base + j] = __float2bfloat16_rn(f - __bfloat162float(h));
        }
    }
}

// ---------------------------------------------------------------------------
// Softmax over contiguous rows of 1024; writes bf16 hi/lo split weights.
// ---------------------------------------------------------------------------
__global__ __launch_bounds__(256) void softmax_split_kernel(const float* __restrict__ sc)
{
    const size_t row = blockIdx.x;
    const float4* p = (const float4*)(sc + row * 1024);
    const int tid = threadIdx.x;
    __shared__ float sh[8];

    float4 v = p[tid];

    float m = fmaxf(fmaxf(v.x, v.y), fmaxf(v.z, v.w));
    #pragma unroll
    for (int o = 16; o; o >>= 1) m = fmaxf(m, __shfl_xor_sync(0xffffffffu, m, o));
    if ((tid & 31) == 0) sh[tid >> 5] = m;
    __syncthreads();
    m = sh[0];
    #pragma unroll
    for (int i = 1; i < 8; i++) m = fmaxf(m, sh[i]);
    __syncthreads();

    v.x = __expf(v.x - m); v.y = __expf(v.y - m);
    v.z = __expf(v.z - m); v.w = __expf(v.w - m);
    float s = v.x + v.y + v.z + v.w;
    #pragma unroll
    for (int o = 16; o; o >>= 1) s += __shfl_xor_sync(0xffffffffu, s, o);
    if ((tid & 31) == 0) sh[tid >> 5] = s;
    __syncthreads();
    s = sh[0] + sh[1] + sh[2] + sh[3] + sh[4] + sh[5] + sh[6] + sh[7];
    const float inv = 1.0f / s;

    float f[4] = {v.x * inv, v.y * inv, v.z * inv, v.w * inv};
    uint32_t hw[2], lw[2];
    #pragma unroll
    for (int q = 0; q < 2; q++) {
        bf16 h0 = __float2bfloat16_rn(f[2 * q]), h1 = __float2bfloat16_rn(f[2 * q + 1]);
        bf16 l0 = __float2bfloat16_rn(f[2 * q] - __bfloat162float(h0));
        bf16 l1 = __float2bfloat16_rn(f[2 * q + 1] - __bfloat162float(h1));
        __nv_bfloat162 hv(h0, h1), lv(l0, l1);
        hw[q] = *(uint32_t*)&hv;
        lw[q] = *(uint32_t*)&lv;
    }
    ((uint2*)(g_wHi + row * 1024))[tid] = make_uint2(hw[0], hw[1]);
    ((uint2*)(g_wLo + row * 1024))[tid] = make_uint2(lw[0], lw[1]);
}

// ---------------------------------------------------------------------------
// Host
// ---------------------------------------------------------------------------
extern "C" void kernel_launch(void* const* d_in, const int* in_sizes, int n_in,
                              void* d_out, int out_size)
{
    const float* src = (const float*)d_in[0];  // (S,B,D)
    const float* tgt = (const float*)d_in[1];  // (T,B,D)
    const float* W1  = (const float*)d_in[2];  // (A,D)
    const float* W2  = (const float*)d_in[3];  // (A,D)
    float* out = (float*)d_out;                // (T,B,D)

    void *srcHi, *srcLo, *tgtHi, *tgtLo, *mtHi, *mtLo, *uHi, *uLo, *sc, *wHi, *wLo;
    cudaGetSymbolAddress(&srcHi, g_srcHi); cudaGetSymbolAddress(&srcLo, g_srcLo);
    cudaGetSymbolAddress(&tgtHi, g_tgtHi); cudaGetSymbolAddress(&tgtLo, g_tgtLo);
    cudaGetSymbolAddress(&mtHi, g_mtHi);   cudaGetSymbolAddress(&mtLo, g_mtLo);
    cudaGetSymbolAddress(&uHi, g_uHi);     cudaGetSymbolAddress(&uLo, g_uLo);
    cudaGetSymbolAddress(&sc, g_sc);
    cudaGetSymbolAddress(&wHi, g_wHi);     cudaGetSymbolAddress(&wLo, g_wLo);

    cudaFuncSetAttribute(mma_gemm<false, true>,  cudaFuncAttributeMaxDynamicSharedMemorySize, SM_TOTAL);
    cudaFuncSetAttribute(mma_gemm<false, false>, cudaFuncAttributeMaxDynamicSharedMemorySize, SM_TOTAL);
    cudaFuncSetAttribute(mma_gemm<true,  false>, cudaFuncAttributeMaxDynamicSharedMemorySize, SM_TOTAL);

    // 1-2. split source & target into bf16 hi/lo
    split_kernel<<<(S_ * B_ * D_ / 4) / 256, 256>>>(src, (bf16*)srcHi, (bf16*)srcLo);
    split_kernel<<<(T_ * B_ * D_ / 4) / 256, 256>>>(tgt, (bf16*)tgtHi, (bf16*)tgtLo);
    // 3. Mt = W2^T W1 (fp32 SIMT), split-stored
    tn_split_kernel<<<dim3(8, 8), 256>>>(W2, W1);

    // 4. u[(s,b), e] = sum_d src[(s,b), d] * Mt[e, d]   (NT, M=32768, split output)
    mma_gemm<false, true><<<dim3(8, 256, 1), 512, SM_TOTAL>>>(
        (const bf16*)srcHi, (const bf16*)srcLo, (const bf16*)mtHi, (const bf16*)mtLo,
        nullptr, (bf16*)uHi, (bf16*)uLo,
        1024, 1024, 1024, 0, 0, 0);

    // 5. scores[b,t,s] = sum_e tgt[t,b,e] * u[s,b,e]   (NT, batched over b)
    mma_gemm<false, false><<<dim3(8, 8, 32), 512, SM_TOTAL>>>(
        (const bf16*)tgtHi, (const bf16*)tgtLo, (const bf16*)uHi, (const bf16*)uLo,
        (float*)sc, nullptr, nullptr,
        32768, 32768, 1024, 1024, 1024, (long)1024 * 1024);

    // 6. softmax over s (+ split weights)
    softmax_split_kernel<<<B_ * T_, 256>>>((const float*)sc);

    // 7. out[t,b,d] = sum_s w[b,t,s] * src[s,b,d]   (A NT, B via ldmatrix.trans)
    mma_gemm<true, false><<<dim3(8, 8, 32), 512, SM_TOTAL>>>(
        (const bf16*)wHi, (const bf16*)wLo, (const bf16*)srcHi, (const bf16*)srcLo,
        out, nullptr, nullptr,
        1024, 32768, 32768, (long)1024 * 1024, 1024, 1024);
}

// round 5
// speedup vs baseline: 3.1538x; 1.0609x over previous
#include <cuda_runtime.h>
#include <cuda_bf16.h>
#include <cstdint>

typedef __nv_bfloat16 bf16;

#define S_ 1024
#define T_ 1024
#define B_ 32
#define D_ 1024
#define A_ 1024

// ---------------------------------------------------------------------------
// Scratch (device globals; allocation is forbidden)
// ---------------------------------------------------------------------------
__device__ __align__(16) bf16 g_srcHi[(size_t)S_ * B_ * D_];   // (S,B,D)
__device__ __align__(16) bf16 g_srcLo[(size_t)S_ * B_ * D_];
__device__ __align__(16) bf16 g_tgtHi[(size_t)T_ * B_ * D_];   // (T,B,D)
__device__ __align__(16) bf16 g_tgtLo[(size_t)T_ * B_ * D_];
__device__ __align__(16) bf16 g_mtHi[(size_t)A_ * D_];         // Mt[e,d] = sum_a W2[a,e]W1[a,d]
__device__ __align__(16) bf16 g_mtLo[(size_t)A_ * D_];
__device__ __align__(16) bf16 g_uHi[(size_t)S_ * B_ * A_];     // (S,B,A) u = src @ Mt^T
__device__ __align__(16) bf16 g_uLo[(size_t)S_ * B_ * A_];
__device__ __align__(16) float g_sc[(size_t)B_ * T_ * S_];     // (B,T,S) scores
__device__ __align__(16) bf16 g_wHi[(size_t)B_ * T_ * S_];     // softmax weights split
__device__ __align__(16) bf16 g_wLo[(size_t)B_ * T_ * S_];

// ---------------------------------------------------------------------------
// Portable tensor-core primitives (sm_80-level PTX: safe for compute_103 pass)
// ---------------------------------------------------------------------------
__device__ __forceinline__ uint32_t smem_u32(const void* p) {
    uint32_t a;
    asm("{ .reg .u64 t; cvta.to.shared.u64 t, %1; cvt.u32.u64 %0, t; }" : "=r"(a) : "l"(p));
    return a;
}

__device__ __forceinline__ void cpa16(uint32_t s, const void* g) {
    asm volatile("cp.async.cg.shared.global [%0], [%1], 16;" :: "r"(s), "l"(g));
}
#define CP_COMMIT() asm volatile("cp.async.commit_group;" ::: "memory")
#define CP_WAIT1()  asm volatile("cp.async.wait_group 1;" ::: "memory")

__device__ __forceinline__ void ldsm4(uint32_t* r, uint32_t a) {
    asm volatile("ldmatrix.sync.aligned.m8n8.x4.shared.b16 {%0,%1,%2,%3}, [%4];"
                 : "=r"(r[0]), "=r"(r[1]), "=r"(r[2]), "=r"(r[3]) : "r"(a));
}
__device__ __forceinline__ void ldsm4t(uint32_t* r, uint32_t a) {
    asm volatile("ldmatrix.sync.aligned.m8n8.x4.trans.shared.b16 {%0,%1,%2,%3}, [%4];"
                 : "=r"(r[0]), "=r"(r[1]), "=r"(r[2]), "=r"(r[3]) : "r"(a));
}
__device__ __forceinline__ void mma_bf16(float* c, const uint32_t* a, const uint32_t* b) {
    asm volatile("mma.sync.aligned.m16n8k16.row.col.f32.bf16.bf16.f32 "
                 "{%0,%1,%2,%3}, {%4,%5,%6,%7}, {%8,%9}, {%0,%1,%2,%3};"
                 : "+f"(c[0]), "+f"(c[1]), "+f"(c[2]), "+f"(c[3])
                 : "r"(a[0]), "r"(a[1]), "r"(a[2]), "r"(a[3]), "r"(b[0]), "r"(b[1]));
}

// ---------------------------------------------------------------------------
// Tiled bf16x3-split GEMM:  C[m,n](z) = sum_k A[m,k]*B[n,k]  (NT)
//   or, if BTRANS:          C[m,n](z) = sum_k A[m,k]*B[k,n]  (B via ldmatrix.trans)
// CTA tile 128x128x64, 16 warps (4x4 -> 32x32 warp tiles), 3-stage cp.async ring,
// register double-buffered fragments across the 4 k16 sub-steps.
// acc += Ahi*Bhi + Ahi*Blo + Alo*Bhi.
// ---------------------------------------------------------------------------
// Tile strides: NT tile = 128 rows x 64 bf16 (128B) padded to 144B/row -> 18432 B
//               TR tile = 64 rows x 128 bf16 (256B) padded to 272B/row -> 17408 B
#define AT_B     18432
#define STAGE_B  73728          // Ahi, Alo, Bhi, Blo (max of variants)
#define SM_TOTAL (3 * STAGE_B)  // 221184 B

__device__ __forceinline__ void load_tile_nt(uint32_t sbase, const bf16* g, long ld, int tid) {
    #pragma unroll
    for (int i = 0; i < 2; i++) {
        const int c = tid + i * 512;              // 1024 chunks of 16B
        const int row = c >> 3, off = (c & 7) * 8;
        cpa16(sbase + row * 144 + off * 2, g + (long)row * ld + off);
    }
}
__device__ __forceinline__ void load_tile_tr(uint32_t sbase, const bf16* g, long ld, int tid) {
    #pragma unroll
    for (int i = 0; i < 2; i++) {
        const int c = tid + i * 512;              // 64 rows x 16 chunks
        const int row = c >> 4, off = (c & 15) * 8;
        cpa16(sbase + row * 272 + off * 2, g + (long)row * ld + off);
    }
}

template <bool BTRANS, bool SPLITOUT>
__global__ __launch_bounds__(512, 1) void mma_gemm(
    const bf16* __restrict__ Ah, const bf16* __restrict__ Al,
    const bf16* __restrict__ Bh, const bf16* __restrict__ Bl,
    float* __restrict__ C, bf16* __restrict__ Oh, bf16* __restrict__ Ol,
    long lda, long ldb, long ldc, long aB, long bB, long cB)
{
    extern __shared__ char smem[];
    const uint32_t sb = smem_u32(smem);
    const int tid = threadIdx.x;
    const int lane = tid & 31, wid = tid >> 5;
    const int wy = wid >> 2, wx = wid & 3;        // 4 x 4 warps, 32x32 tiles
    const long m0 = (long)blockIdx.y * 128;
    const long n0 = (long)blockIdx.x * 128;
    const long z  = blockIdx.z;

    const bf16* pAh = Ah + z * aB + m0 * lda;
    const bf16* pAl = Al + z * aB + m0 * lda;
    const bf16* pBh = BTRANS ? (Bh + z * bB + n0) : (Bh + z * bB + n0 * ldb);
    const bf16* pBl = BTRANS ? (Bl + z * bB + n0) : (Bl + z * bB + n0 * ldb);

    float acc[2][4][4] = {};

    auto LOAD = [&](int chunk) {
        const uint32_t st = sb + (chunk % 3) * STAGE_B;
        const long k0 = (long)chunk * 64;
        load_tile_nt(st,            pAh + k0, lda, tid);
        load_tile_nt(st + AT_B,     pAl + k0, lda, tid);
        if (BTRANS) {
            load_tile_tr(st + 2 * AT_B,         pBh + k0 * ldb, ldb, tid);
            load_tile_tr(st + 2 * AT_B + 17408, pBl + k0 * ldb, ldb, tid);
        } else {
            load_tile_nt(st + 2 * AT_B,        pBh + k0, ldb, tid);
            load_tile_nt(st + 2 * AT_B + AT_B, pBl + k0, ldb, tid);
        }
    };

    // Per-warp fragment addresses (k16-invariant parts)
    const uint32_t aRow0 = (uint32_t)(wy * 32 + (lane & 15)) * 144 + ((lane >> 4) << 4);
    const uint32_t bRowNT0 = (uint32_t)(wx * 32 + (lane & 7) + ((lane >> 4) << 3)) * 144
                           + (((lane >> 3) & 1) << 4);
    const uint32_t bColTR = (uint32_t)(wx * 32 + ((lane >> 4) << 3)) * 2;
    const uint32_t bRowTR0 = (uint32_t)((lane & 7) + ((lane >> 3) & 1) * 8) * 272;

    // Fragment double buffers
    uint32_t ah[2][2][4], al[2][2][4], bh[2][8], bl[2][8];

    auto LDFRAG = [&](uint32_t st, int k16, int buf) {
        const uint32_t kb = (uint32_t)k16 * 32;
        #pragma unroll
        for (int mt = 0; mt < 2; mt++) {
            const uint32_t ad = st + aRow0 + (uint32_t)mt * 16 * 144 + kb;
            ldsm4(ah[buf][mt], ad);
            ldsm4(al[buf][mt], ad + AT_B);
        }
        if (!BTRANS) {
            #pragma unroll
            for (int p = 0; p < 2; p++) {
                const uint32_t bd = st + 2 * AT_B + bRowNT0 + (uint32_t)p * 16 * 144 + kb;
                ldsm4(&bh[buf][p * 4], bd);
                ldsm4(&bl[buf][p * 4], bd + AT_B);
            }
        } else {
            #pragma unroll
            for (int p = 0; p < 2; p++) {
                const uint32_t bd = st + 2 * AT_B + bRowTR0 + (uint32_t)k16 * 16 * 272
                                  + bColTR + (uint32_t)p * 32;
                ldsm4t(&bh[buf][p * 4], bd);
                ldsm4t(&bl[buf][p * 4], bd + 17408);
            }
        }
    };

    LOAD(0); CP_COMMIT();
    LOAD(1); CP_COMMIT();

    const int NC = 16;   // K = 1024 / 64
    for (int c = 0; c < NC; c++) {
        CP_WAIT1();                       // chunk c resident (c+1 may fly)
        __syncthreads();                  // all warps done with stage (c-1)%3
        if (c + 2 < NC) LOAD(c + 2);      // refill stage (c-1)%3
        CP_COMMIT();
        const uint32_t st = sb + (c % 3) * STAGE_B;

        LDFRAG(st, 0, 0);
        #pragma unroll
        for (int k16 = 0; k16 < 4; k16++) {
            const int cur = k16 & 1, nxt = cur ^ 1;
            if (k16 < 3) LDFRAG(st, k16 + 1, nxt);
            #pragma unroll
            for (int mt = 0; mt < 2; mt++)
                #pragma unroll
                for (int nt = 0; nt < 4; nt++) {
                    mma_bf16(acc[mt][nt], ah[cur][mt], &bh[cur][nt * 2]);
                    mma_bf16(acc[mt][nt], ah[cur][mt], &bl[cur][nt * 2]);
                    mma_bf16(acc[mt][nt], al[cur][mt], &bh[cur][nt * 2]);
                }
        }
    }

    // Epilogue (registers -> gmem)
    #pragma unroll
    for (int mt = 0; mt < 2; mt++) {
        #pragma unroll
        for (int half = 0; half < 2; half++) {
            const long row = m0 + wy * 32 + mt * 16 + (lane >> 2) + half * 8;
            #pragma unroll
            for (int nt = 0; nt < 4; nt++) {
                const long col = n0 + wx * 32 + nt * 8 + (lane & 3) * 2;
                const float v0 = acc[mt][nt][half * 2 + 0];
                const float v1 = acc[mt][nt][half * 2 + 1];
                if (SPLITOUT) {
                    bf16 h0 = __float2bfloat16_rn(v0), h1 = __float2bfloat16_rn(v1);
                    bf16 l0 = __float2bfloat16_rn(v0 - __bfloat162float(h0));
                    bf16 l1 = __float2bfloat16_rn(v1 - __bfloat162float(h1));
                    __nv_bfloat162 hv(h0, h1), lv(l0, l1);
                    *(uint32_t*)(Oh + z * cB + row * ldc + col) = *(uint32_t*)&hv;
                    *(uint32_t*)(Ol + z * cB + row * ldc + col) = *(uint32_t*)&lv;
                } else {
                    *(float2*)(C + z * cB + row * ldc + col) = make_float2(v0, v1);
                }
            }
        }
    }
}

// ---------------------------------------------------------------------------
// Elementwise fp32 -> bf16 hi/lo split
// ---------------------------------------------------------------------------
__global__ __launch_bounds__(256) void split_kernel(
    const float* __restrict__ x, bf16* __restrict__ hi, bf16* __restrict__ lo)
{
    const size_t i4 = (size_t)blockIdx.x * 256 + threadIdx.x;
    float4 v = ((const float4*)x)[i4];
    float f[4] = {v.x, v.y, v.z, v.w};
    uint32_t hw[2], lw[2];
    #pragma unroll
    for (int p = 0; p < 2; p++) {
        bf16 h0 = __float2bfloat16_rn(f[2 * p]), h1 = __float2bfloat16_rn(f[2 * p + 1]);
        bf16 l0 = __float2bfloat16_rn(f[2 * p] - __bfloat162float(h0));
        bf16 l1 = __float2bfloat16_rn(f[2 * p + 1] - __bfloat162float(h1));
        __nv_bfloat162 hv(h0, h1), lv(l0, l1);
        hw[p] = *(uint32_t*)&hv;
        lw[p] = *(uint32_t*)&lv;
    }
    ((uint2*)hi)[i4] = make_uint2(hw[0], hw[1]);
    ((uint2*)lo)[i4] = make_uint2(lw[0], lw[1]);
}

// ---------------------------------------------------------------------------
// TN SIMT fp32 GEMM: Mt[e,d] = sum_a W2[a,e]*W1[a,d], split-stored (2 GFLOP)
// ---------------------------------------------------------------------------
__global__ __launch_bounds__(256) void tn_split_kernel(
    const float* __restrict__ W2, const float* __restrict__ W1)
{
    __shared__ float As[16][128];
    __shared__ float Bs[16][128];

    const int tid = threadIdx.x;
    const int tx = tid & 15, ty = tid >> 4;
    const int m0 = blockIdx.y * 128, n0 = blockIdx.x * 128;
    const int r8 = tid >> 5, c4 = (tid & 31) * 4;

    float acc[8][8] = {};

    for (int k0 = 0; k0 < 1024; k0 += 16) {
        #pragma unroll
        for (int i = 0; i < 2; i++) {
            const int kr = k0 + r8 + i * 8;
            *(float4*)&As[r8 + i * 8][c4] = *(const float4*)(W2 + (size_t)kr * 1024 + m0 + c4);
            *(float4*)&Bs[r8 + i * 8][c4] = *(const float4*)(W1 + (size_t)kr * 1024 + n0 + c4);
        }
        __syncthreads();
        #pragma unroll
        for (int kk = 0; kk < 16; kk++) {
            float ra[8], rb[8];
            *(float4*)&ra[0] = *(const float4*)&As[kk][ty * 8];
            *(float4*)&ra[4] = *(const float4*)&As[kk][ty * 8 + 4];
            *(float4*)&rb[0] = *(const float4*)&Bs[kk][tx * 8];
            *(float4*)&rb[4] = *(const float4*)&Bs[kk][tx * 8 + 4];
            #pragma unroll
            for (int i = 0; i < 8; i++)
                #pragma unroll
                for (int j = 0; j < 8; j++)
                    acc[i][j] = fmaf(ra[i], rb[j], acc[i][j]);
        }
        __syncthreads();
    }

    #pragma unroll
    for (int i = 0; i < 8; i++) {
        const size_t base = (size_t)(m0 + ty * 8 + i) * 1024 + n0 + tx * 8;
        #pragma unroll
        for (int j = 0; j < 8; j++) {
            float f = acc[i][j];
            bf16 h = __float2bfloat16_rn(f);
            g_mtHi[base + j] = h;
            g_mtLo[base + j] = __float2bfloat16_rn(f - __bfloat162float(h));
        }
    }
}

// ---------------------------------------------------------------------------
// Softmax over contiguous rows of 1024; writes bf16 hi/lo split weights.
// ---------------------------------------------------------------------------
__global__ __launch_bounds__(256) void softmax_split_kernel(const float* __restrict__ sc)
{
    const size_t row = blockIdx.x;
    const float4* p = (const float4*)(sc + row * 1024);
    const int tid = threadIdx.x;
    __shared__ float sh[8];

    float4 v = p[tid];

    float m = fmaxf(fmaxf(v.x, v.y), fmaxf(v.z, v.w));
    #pragma unroll
    for (int o = 16; o; o >>= 1) m = fmaxf(m, __shfl_xor_sync(0xffffffffu, m, o));
    if ((tid & 31) == 0) sh[tid >> 5] = m;
    __syncthreads();
    m = sh[0];
    #pragma unroll
    for (int i = 1; i < 8; i++) m = fmaxf(m, sh[i]);
    __syncthreads();

    v.x = __expf(v.x - m); v.y = __expf(v.y - m);
    v.z = __expf(v.z - m); v.w = __expf(v.w - m);
    float s = v.x + v.y + v.z + v.w;
    #pragma unroll
    for (int o = 16; o; o >>= 1) s += __shfl_xor_sync(0xffffffffu, s, o);
    if ((tid & 31) == 0) sh[tid >> 5] = s;
    __syncthreads();
    s = sh[0] + sh[1] + sh[2] + sh[3] + sh[4] + sh[5] + sh[6] + sh[7];
    const float inv = 1.0f / s;

    float f[4] = {v.x * inv, v.y * inv, v.z * inv, v.w * inv};
    uint32_t hw[2], lw[2];
    #pragma unroll
    for (int q = 0; q < 2; q++) {
        bf16 h0 = __float2bfloat16_rn(f[2 * q]), h1 = __float2bfloat16_rn(f[2 * q + 1]);
        bf16 l0 = __float2bfloat16_rn(f[2 * q] - __bfloat162float(h0));
        bf16 l1 = __float2bfloat16_rn(f[2 * q + 1] - __bfloat162float(h1));
        __nv_bfloat162 hv(h0, h1), lv(l0, l1);
        hw[q] = *(uint32_t*)&hv;
        lw[q] = *(uint32_t*)&lv;
    }
    ((uint2*)(g_wHi + row * 1024))[tid] = make_uint2(hw[0], hw[1]);
    ((uint2*)(g_wLo + row * 1024))[tid] = make_uint2(lw[0], lw[1]);
}

// ---------------------------------------------------------------------------
// Host
// ---------------------------------------------------------------------------
extern "C" void kernel_launch(void* const* d_in, const int* in_sizes, int n_in,
                              void* d_out, int out_size)
{
    const float* src = (const float*)d_in[0];  // (S,B,D)
    const float* tgt = (const float*)d_in[1];  // (T,B,D)
    const float* W1  = (const float*)d_in[2];  // (A,D)
    const float* W2  = (const float*)d_in[3];  // (A,D)
    float* out = (float*)d_out;                // (T,B,D)

    void *srcHi, *srcLo, *tgtHi, *tgtLo, *mtHi, *mtLo, *uHi, *uLo, *sc, *wHi, *wLo;
    cudaGetSymbolAddress(&srcHi, g_srcHi); cudaGetSymbolAddress(&srcLo, g_srcLo);
    cudaGetSymbolAddress(&tgtHi, g_tgtHi); cudaGetSymbolAddress(&tgtLo, g_tgtLo);
    cudaGetSymbolAddress(&mtHi, g_mtHi);   cudaGetSymbolAddress(&mtLo, g_mtLo);
    cudaGetSymbolAddress(&uHi, g_uHi);     cudaGetSymbolAddress(&uLo, g_uLo);
    cudaGetSymbolAddress(&sc, g_sc);
    cudaGetSymbolAddress(&wHi, g_wHi);     cudaGetSymbolAddress(&wLo, g_wLo);

    cudaFuncSetAttribute(mma_gemm<false, true>,  cudaFuncAttributeMaxDynamicSharedMemorySize, SM_TOTAL);
    cudaFuncSetAttribute(mma_gemm<false, false>, cudaFuncAttributeMaxDynamicSharedMemorySize, SM_TOTAL);
    cudaFuncSetAttribute(mma_gemm<true,  false>, cudaFuncAttributeMaxDynamicSharedMemorySize, SM_TOTAL);

    // 1-2. split source & target into bf16 hi/lo
    split_kernel<<<(S_ * B_ * D_ / 4) / 256, 256>>>(src, (bf16*)srcHi, (bf16*)srcLo);
    split_kernel<<<(T_ * B_ * D_ / 4) / 256, 256>>>(tgt, (bf16*)tgtHi, (bf16*)tgtLo);
    // 3. Mt = W2^T W1 (fp32 SIMT), split-stored
    tn_split_kernel<<<dim3(8, 8), 256>>>(W2, W1);

    // 4. u[(s,b), e] = sum_d src[(s,b), d] * Mt[e, d]   (NT, M=32768, split output)
    mma_gemm<false, true><<<dim3(8, 256, 1), 512, SM_TOTAL>>>(
        (const bf16*)srcHi, (const bf16*)srcLo, (const bf16*)mtHi, (const bf16*)mtLo,
        nullptr, (bf16*)uHi, (bf16*)uLo,
        1024, 1024, 1024, 0, 0, 0);

    // 5. scores[b,t,s] = sum_e tgt[t,b,e] * u[s,b,e]   (NT, batched over b)
    mma_gemm<false, false><<<dim3(8, 8, 32), 512, SM_TOTAL>>>(
        (const bf16*)tgtHi, (const bf16*)tgtLo, (const bf16*)uHi, (const bf16*)uLo,
        (float*)sc, nullptr, nullptr,
        32768, 32768, 1024, 1024, 1024, (long)1024 * 1024);

    // 6. softmax over s (+ split weights)
    softmax_split_kernel<<<B_ * T_, 256>>>((const float*)sc);

    // 7. out[t,b,d] = sum_s w[b,t,s] * src[s,b,d]   (A NT, B via ldmatrix.trans)
    mma_gemm<true, false><<<dim3(8, 8, 32), 512, SM_TOTAL>>>(
        (const bf16*)wHi, (const bf16*)wLo, (const bf16*)srcHi, (const bf16*)srcLo,
        out, nullptr, nullptr,
        1024, 32768, 32768, (long)1024 * 1024, 1024, 1024);
}

// round 6
// speedup vs baseline: 3.3897x; 1.0748x over previous
#include <cuda_runtime.h>
#include <cuda_bf16.h>
#include <cstdint>

typedef __nv_bfloat16 bf16;

#define S_ 1024
#define T_ 1024
#define B_ 32
#define D_ 1024
#define A_ 1024

// ---------------------------------------------------------------------------
// Scratch (device globals; allocation is forbidden)
// ---------------------------------------------------------------------------
__device__ __align__(16) bf16 g_srcHi[(size_t)S_ * B_ * D_];   // (S,B,D)
__device__ __align__(16) bf16 g_srcLo[(size_t)S_ * B_ * D_];
__device__ __align__(16) bf16 g_tgtHi[(size_t)T_ * B_ * D_];   // (T,B,D)
__device__ __align__(16) bf16 g_tgtLo[(size_t)T_ * B_ * D_];
__device__ __align__(16) bf16 g_mtHi[(size_t)A_ * D_];         // Mt[e,d] = sum_a W2[a,e]W1[a,d]
__device__ __align__(16) bf16 g_mtLo[(size_t)A_ * D_];
__device__ __align__(16) bf16 g_uHi[(size_t)S_ * B_ * A_];     // (S,B,A) u = src @ Mt^T
__device__ __align__(16) bf16 g_uLo[(size_t)S_ * B_ * A_];
__device__ __align__(16) float g_sc[(size_t)B_ * T_ * S_];     // (B,T,S) scores
__device__ __align__(16) bf16 g_wHi[(size_t)B_ * T_ * S_];     // softmax weights split
__device__ __align__(16) bf16 g_wLo[(size_t)B_ * T_ * S_];

// ---------------------------------------------------------------------------
// Portable tensor-core primitives (sm_80-level PTX: safe for compute_103 pass)
// ---------------------------------------------------------------------------
__device__ __forceinline__ uint32_t smem_u32(const void* p) {
    uint32_t a;
    asm("{ .reg .u64 t; cvta.to.shared.u64 t, %1; cvt.u32.u64 %0, t; }" : "=r"(a) : "l"(p));
    return a;
}

__device__ __forceinline__ void cpa16(uint32_t s, const void* g) {
    asm volatile("cp.async.cg.shared.global [%0], [%1], 16;" :: "r"(s), "l"(g));
}
#define CP_COMMIT() asm volatile("cp.async.commit_group;" ::: "memory")
#define CP_WAIT1()  asm volatile("cp.async.wait_group 1;" ::: "memory")

__device__ __forceinline__ void ldsm4(uint32_t* r, uint32_t a) {
    asm volatile("ldmatrix.sync.aligned.m8n8.x4.shared.b16 {%0,%1,%2,%3}, [%4];"
                 : "=r"(r[0]), "=r"(r[1]), "=r"(r[2]), "=r"(r[3]) : "r"(a));
}
__device__ __forceinline__ void ldsm4t(uint32_t* r, uint32_t a) {
    asm volatile("ldmatrix.sync.aligned.m8n8.x4.trans.shared.b16 {%0,%1,%2,%3}, [%4];"
                 : "=r"(r[0]), "=r"(r[1]), "=r"(r[2]), "=r"(r[3]) : "r"(a));
}
__device__ __forceinline__ void mma_bf16(float* c, const uint32_t* a, const uint32_t* b) {
    asm volatile("mma.sync.aligned.m16n8k16.row.col.f32.bf16.bf16.f32 "
                 "{%0,%1,%2,%3}, {%4,%5,%6,%7}, {%8,%9}, {%0,%1,%2,%3};"
                 : "+f"(c[0]), "+f"(c[1]), "+f"(c[2]), "+f"(c[3])
                 : "r"(a[0]), "r"(a[1]), "r"(a[2]), "r"(a[3]), "r"(b[0]), "r"(b[1]));
}

// ---------------------------------------------------------------------------
// Tiled bf16x3-split GEMM:  C[m,n](z) = sum_k A[m,k]*B[n,k]  (NT)
//   or, if BTRANS:          C[m,n](z) = sum_k A[m,k]*B[k,n]  (B via ldmatrix.trans)
// CTA tile 256x128x32, 16 warps (4x4 grid of 64x32 warp tiles), 3-stage ring.
// acc += Ahi*Bhi + Ahi*Blo + Alo*Bhi.
// ---------------------------------------------------------------------------
// A tile (per half): 256 rows x 32 bf16, row stride 80B -> 20480 B
// B NT tile:         128 rows x 32 bf16, row stride 80B -> 10240 B
// B TR tile:          32 rows x 128 bf16, row stride 272B -> 8704 B
#define A_HALF   20480
#define BNT_HALF 10240
#define BTR_HALF 8704
#define STAGE_B  61440          // Ahi+Alo (40960) + Bhi+Blo (<=20480)
#define SM_TOTAL (3 * STAGE_B)  // 184320 B

__device__ __forceinline__ void load_A(uint32_t sbase, const bf16* g, long ld, int tid) {
    #pragma unroll
    for (int i = 0; i < 2; i++) {
        const int c = tid + i * 512;              // 1024 chunks of 16B
        const int row = c >> 2, off = (c & 3) * 8;
        cpa16(sbase + row * 80 + off * 2, g + (long)row * ld + off);
    }
}
__device__ __forceinline__ void load_B_nt(uint32_t sbase, const bf16* g, long ld, int tid) {
    const int row = tid >> 2, off = (tid & 3) * 8;  // 512 chunks of 16B
    cpa16(sbase + row * 80 + off * 2, g + (long)row * ld + off);
}
__device__ __forceinline__ void load_B_tr(uint32_t sbase, const bf16* g, long ld, int tid) {
    const int row = tid >> 4, off = (tid & 15) * 8; // 32 rows x 16 chunks
    cpa16(sbase + row * 272 + off * 2, g + (long)row * ld + off);
}

template <bool BTRANS, bool SPLITOUT>
__global__ __launch_bounds__(512, 1) void mma_gemm(
    const bf16* __restrict__ Ah, const bf16* __restrict__ Al,
    const bf16* __restrict__ Bh, const bf16* __restrict__ Bl,
    float* __restrict__ C, bf16* __restrict__ Oh, bf16* __restrict__ Ol,
    long lda, long ldb, long ldc, long aB, long bB, long cB)
{
    extern __shared__ char smem[];
    const uint32_t sb = smem_u32(smem);
    const int tid = threadIdx.x;
    const int lane = tid & 31, wid = tid >> 5;
    const int wy = wid >> 2, wx = wid & 3;        // 4 x 4 warps, 64x32 tiles
    const long m0 = (long)blockIdx.y * 256;
    const long n0 = (long)blockIdx.x * 128;
    const long z  = blockIdx.z;

    const bf16* pAh = Ah + z * aB + m0 * lda;
    const bf16* pAl = Al + z * aB + m0 * lda;
    const bf16* pBh = BTRANS ? (Bh + z * bB + n0) : (Bh + z * bB + n0 * ldb);
    const bf16* pBl = BTRANS ? (Bl + z * bB + n0) : (Bl + z * bB + n0 * ldb);

    float acc[4][4][4] = {};

    auto LOAD = [&](int chunk) {
        const uint32_t st = sb + (chunk % 3) * STAGE_B;
        const long k0 = (long)chunk * 32;
        load_A(st,          pAh + k0, lda, tid);
        load_A(st + A_HALF, pAl + k0, lda, tid);
        if (BTRANS) {
            load_B_tr(st + 2 * A_HALF,            pBh + k0 * ldb, ldb, tid);
            load_B_tr(st + 2 * A_HALF + BTR_HALF, pBl + k0 * ldb, ldb, tid);
        } else {
            load_B_nt(st + 2 * A_HALF,            pBh + k0, ldb, tid);
            load_B_nt(st + 2 * A_HALF + BNT_HALF, pBl + k0, ldb, tid);
        }
    };

    // k16-invariant address parts
    const uint32_t aRow0   = (uint32_t)(wy * 64 + (lane & 15)) * 80 + ((lane >> 4) << 4);
    const uint32_t bRowNT0 = (uint32_t)(wx * 32 + (lane & 7) + ((lane >> 4) << 3)) * 80
                           + (((lane >> 3) & 1) << 4);
    const uint32_t bColTR  = (uint32_t)(wx * 32 + ((lane >> 4) << 3)) * 2;
    const uint32_t bRowTR0 = (uint32_t)((lane & 7) + ((lane >> 3) & 1) * 8) * 272;

    LOAD(0); CP_COMMIT();
    LOAD(1); CP_COMMIT();

    const int NC = 32;   // K = 1024 / 32
    for (int c = 0; c < NC; c++) {
        CP_WAIT1();                       // chunk c resident (c+1 may fly)
        __syncthreads();                  // all warps done with stage (c-1)%3
        if (c + 2 < NC) LOAD(c + 2);      // refill stage (c-1)%3
        CP_COMMIT();
        const uint32_t st = sb + (c % 3) * STAGE_B;

        #pragma unroll
        for (int k16 = 0; k16 < 2; k16++) {
            const uint32_t kb = (uint32_t)k16 * 32;
            uint32_t bh[8], bl[8];
            if (!BTRANS) {
                #pragma unroll
                for (int p = 0; p < 2; p++) {
                    const uint32_t bd = st + 2 * A_HALF + bRowNT0 + (uint32_t)p * 16 * 80 + kb;
                    ldsm4(&bh[p * 4], bd);
                    ldsm4(&bl[p * 4], bd + BNT_HALF);
                }
            } else {
                #pragma unroll
                for (int p = 0; p < 2; p++) {
                    const uint32_t bd = st + 2 * A_HALF + bRowTR0 + (uint32_t)k16 * 16 * 272
                                      + bColTR + (uint32_t)p * 32;
                    ldsm4t(&bh[p * 4], bd);
                    ldsm4t(&bl[p * 4], bd + BTR_HALF);
                }
            }
            #pragma unroll
            for (int mt = 0; mt < 4; mt++) {
                uint32_t ah[4], al[4];
                const uint32_t ad = st + aRow0 + (uint32_t)mt * 16 * 80 + kb;
                ldsm4(ah, ad);
                ldsm4(al, ad + A_HALF);
                #pragma unroll
                for (int nt = 0; nt < 4; nt++) {
                    mma_bf16(acc[mt][nt], ah, &bh[nt * 2]);
                    mma_bf16(acc[mt][nt], ah, &bl[nt * 2]);
                    mma_bf16(acc[mt][nt], al, &bh[nt * 2]);
                }
            }
        }
    }

    // Epilogue (registers -> gmem)
    #pragma unroll
    for (int mt = 0; mt < 4; mt++) {
        #pragma unroll
        for (int half = 0; half < 2; half++) {
            const long row = m0 + wy * 64 + mt * 16 + (lane >> 2) + half * 8;
            #pragma unroll
            for (int nt = 0; nt < 4; nt++) {
                const long col = n0 + wx * 32 + nt * 8 + (lane & 3) * 2;
                const float v0 = acc[mt][nt][half * 2 + 0];
                const float v1 = acc[mt][nt][half * 2 + 1];
                if (SPLITOUT) {
                    bf16 h0 = __float2bfloat16_rn(v0), h1 = __float2bfloat16_rn(v1);
                    bf16 l0 = __float2bfloat16_rn(v0 - __bfloat162float(h0));
                    bf16 l1 = __float2bfloat16_rn(v1 - __bfloat162float(h1));
                    __nv_bfloat162 hv(h0, h1), lv(l0, l1);
                    *(uint32_t*)(Oh + z * cB + row * ldc + col) = *(uint32_t*)&hv;
                    *(uint32_t*)(Ol + z * cB + row * ldc + col) = *(uint32_t*)&lv;
                } else {
                    *(float2*)(C + z * cB + row * ldc + col) = make_float2(v0, v1);
                }
            }
        }
    }
}

// ---------------------------------------------------------------------------
// Elementwise fp32 -> bf16 hi/lo split
// ---------------------------------------------------------------------------
__global__ __launch_bounds__(256) void split_kernel(
    const float* __restrict__ x, bf16* __restrict__ hi, bf16* __restrict__ lo)
{
    const size_t i4 = (size_t)blockIdx.x * 256 + threadIdx.x;
    float4 v = ((const float4*)x)[i4];
    float f[4] = {v.x, v.y, v.z, v.w};
    uint32_t hw[2], lw[2];
    #pragma unroll
    for (int p = 0; p < 2; p++) {
        bf16 h0 = __float2bfloat16_rn(f[2 * p]), h1 = __float2bfloat16_rn(f[2 * p + 1]);
        bf16 l0 = __float2bfloat16_rn(f[2 * p] - __bfloat162float(h0));
        bf16 l1 = __float2bfloat16_rn(f[2 * p + 1] - __bfloat162float(h1));
        __nv_bfloat162 hv(h0, h1), lv(l0, l1);
        hw[p] = *(uint32_t*)&hv;
        lw[p] = *(uint32_t*)&lv;
    }
    ((uint2*)hi)[i4] = make_uint2(hw[0], hw[1]);
    ((uint2*)lo)[i4] = make_uint2(lw[0], lw[1]);
}

// ---------------------------------------------------------------------------
// TN SIMT fp32 GEMM: Mt[e,d] = sum_a W2[a,e]*W1[a,d], split-stored (2 GFLOP)
// ---------------------------------------------------------------------------
__global__ __launch_bounds__(256) void tn_split_kernel(
    const float* __restrict__ W2, const float* __restrict__ W1)
{
    __shared__ float As[16][128];
    __shared__ float Bs[16][128];

    const int tid = threadIdx.x;
    const int tx = tid & 15, ty = tid >> 4;
    const int m0 = blockIdx.y * 128, n0 = blockIdx.x * 128;
    const int r8 = tid >> 5, c4 = (tid & 31) * 4;

    float acc[8][8] = {};

    for (int k0 = 0; k0 < 1024; k0 += 16) {
        #pragma unroll
        for (int i = 0; i < 2; i++) {
            const int kr = k0 + r8 + i * 8;
            *(float4*)&As[r8 + i * 8][c4] = *(const float4*)(W2 + (size_t)kr * 1024 + m0 + c4);
            *(float4*)&Bs[r8 + i * 8][c4] = *(const float4*)(W1 + (size_t)kr * 1024 + n0 + c4);
        }
        __syncthreads();
        #pragma unroll
        for (int kk = 0; kk < 16; kk++) {
            float ra[8], rb[8];
            *(float4*)&ra[0] = *(const float4*)&As[kk][ty * 8];
            *(float4*)&ra[4] = *(const float4*)&As[kk][ty * 8 + 4];
            *(float4*)&rb[0] = *(const float4*)&Bs[kk][tx * 8];
            *(float4*)&rb[4] = *(const float4*)&Bs[kk][tx * 8 + 4];
            #pragma unroll
            for (int i = 0; i < 8; i++)
                #pragma unroll
                for (int j = 0; j < 8; j++)
                    acc[i][j] = fmaf(ra[i], rb[j], acc[i][j]);
        }
        __syncthreads();
    }

    #pragma unroll
    for (int i = 0; i < 8; i++) {
        const size_t base = (size_t)(m0 + ty * 8 + i) * 1024 + n0 + tx * 8;
        #pragma unroll
        for (int j = 0; j < 8; j++) {
            float f = acc[i][j];
            bf16 h = __float2bfloat16_rn(f);
            g_mtHi[base + j] = h;
            g_mtLo[base + j] = __float2bfloat16_rn(f - __bfloat162float(h));
        }
    }
}

// ---------------------------------------------------------------------------
// Softmax over contiguous rows of 1024; writes bf16 hi/lo split weights.
// ---------------------------------------------------------------------------
__global__ __launch_bounds__(256) void softmax_split_kernel(const float* __restrict__ sc)
{
    const size_t row = blockIdx.x;
    const float4* p = (const float4*)(sc + row * 1024);
    const int tid = threadIdx.x;
    __shared__ float sh[8];

    float4 v = p[tid];

    float m = fmaxf(fmaxf(v.x, v.y), fmaxf(v.z, v.w));
    #pragma unroll
    for (int o = 16; o; o >>= 1) m = fmaxf(m, __shfl_xor_sync(0xffffffffu, m, o));
    if ((tid & 31) == 0) sh[tid >> 5] = m;
    __syncthreads();
    m = sh[0];
    #pragma unroll
    for (int i = 1; i < 8; i++) m = fmaxf(m, sh[i]);
    __syncthreads();

    v.x = __expf(v.x - m); v.y = __expf(v.y - m);
    v.z = __expf(v.z - m); v.w = __expf(v.w - m);
    float s = v.x + v.y + v.z + v.w;
    #pragma unroll
    for (int o = 16; o; o >>= 1) s += __shfl_xor_sync(0xffffffffu, s, o);
    if ((tid & 31) == 0) sh[tid >> 5] = s;
    __syncthreads();
    s = sh[0] + sh[1] + sh[2] + sh[3] + sh[4] + sh[5] + sh[6] + sh[7];
    const float inv = 1.0f / s;

    float f[4] = {v.x * inv, v.y * inv, v.z * inv, v.w * inv};
    uint32_t hw[2], lw[2];
    #pragma unroll
    for (int q = 0; q < 2; q++) {
        bf16 h0 = __float2bfloat16_rn(f[2 * q]), h1 = __float2bfloat16_rn(f[2 * q + 1]);
        bf16 l0 = __float2bfloat16_rn(f[2 * q] - __bfloat162float(h0));
        bf16 l1 = __float2bfloat16_rn(f[2 * q + 1] - __bfloat162float(h1));
        __nv_bfloat162 hv(h0, h1), lv(l0, l1);
        hw[q] = *(uint32_t*)&hv;
        lw[q] = *(uint32_t*)&lv;
    }
    ((uint2*)(g_wHi + row * 1024))[tid] = make_uint2(hw[0], hw[1]);
    ((uint2*)(g_wLo + row * 1024))[tid] = make_uint2(lw[0], lw[1]);
}

// ---------------------------------------------------------------------------
// Host
// ---------------------------------------------------------------------------
extern "C" void kernel_launch(void* const* d_in, const int* in_sizes, int n_in,
                              void* d_out, int out_size)
{
    const float* src = (const float*)d_in[0];  // (S,B,D)
    const float* tgt = (const float*)d_in[1];  // (T,B,D)
    const float* W1  = (const float*)d_in[2];  // (A,D)
    const float* W2  = (const float*)d_in[3];  // (A,D)
    float* out = (float*)d_out;                // (T,B,D)

    void *srcHi, *srcLo, *tgtHi, *tgtLo, *mtHi, *mtLo, *uHi, *uLo, *sc, *wHi, *wLo;
    cudaGetSymbolAddress(&srcHi, g_srcHi); cudaGetSymbolAddress(&srcLo, g_srcLo);
    cudaGetSymbolAddress(&tgtHi, g_tgtHi); cudaGetSymbolAddress(&tgtLo, g_tgtLo);
    cudaGetSymbolAddress(&mtHi, g_mtHi);   cudaGetSymbolAddress(&mtLo, g_mtLo);
    cudaGetSymbolAddress(&uHi, g_uHi);     cudaGetSymbolAddress(&uLo, g_uLo);
    cudaGetSymbolAddress(&sc, g_sc);
    cudaGetSymbolAddress(&wHi, g_wHi);     cudaGetSymbolAddress(&wLo, g_wLo);

    cudaFuncSetAttribute(mma_gemm<false, true>,  cudaFuncAttributeMaxDynamicSharedMemorySize, SM_TOTAL);
    cudaFuncSetAttribute(mma_gemm<false, false>, cudaFuncAttributeMaxDynamicSharedMemorySize, SM_TOTAL);
    cudaFuncSetAttribute(mma_gemm<true,  false>, cudaFuncAttributeMaxDynamicSharedMemorySize, SM_TOTAL);

    // 1-2. split source & target into bf16 hi/lo
    split_kernel<<<(S_ * B_ * D_ / 4) / 256, 256>>>(src, (bf16*)srcHi, (bf16*)srcLo);
    split_kernel<<<(T_ * B_ * D_ / 4) / 256, 256>>>(tgt, (bf16*)tgtHi, (bf16*)tgtLo);
    // 3. Mt = W2^T W1 (fp32 SIMT), split-stored
    tn_split_kernel<<<dim3(8, 8), 256>>>(W2, W1);

    // 4. u[(s,b), e] = sum_d src[(s,b), d] * Mt[e, d]   (NT, M=32768, split output)
    mma_gemm<false, true><<<dim3(8, 128, 1), 512, SM_TOTAL>>>(
        (const bf16*)srcHi, (const bf16*)srcLo, (const bf16*)mtHi, (const bf16*)mtLo,
        nullptr, (bf16*)uHi, (bf16*)uLo,
        1024, 1024, 1024, 0, 0, 0);

    // 5. scores[b,t,s] = sum_e tgt[t,b,e] * u[s,b,e]   (NT, batched over b)
    mma_gemm<false, false><<<dim3(8, 4, 32), 512, SM_TOTAL>>>(
        (const bf16*)tgtHi, (const bf16*)tgtLo, (const bf16*)uHi, (const bf16*)uLo,
        (float*)sc, nullptr, nullptr,
        32768, 32768, 1024, 1024, 1024, (long)1024 * 1024);

    // 6. softmax over s (+ split weights)
    softmax_split_kernel<<<B_ * T_, 256>>>((const float*)sc);

    // 7. out[t,b,d] = sum_s w[b,t,s] * src[s,b,d]   (A NT, B via ldmatrix.trans)
    mma_gemm<true, false><<<dim3(8, 4, 32), 512, SM_TOTAL>>>(
        (const bf16*)wHi, (const bf16*)wLo, (const bf16*)srcHi, (const bf16*)srcLo,
        out, nullptr, nullptr,
        1024, 32768, 32768, (long)1024 * 1024, 1024, 1024);
}